// round 4
// baseline (speedup 1.0000x reference)
#include <cuda_runtime.h>
#include <stdint.h>

// Fp8Unpadding: gather valid rows out of 256-padded groups.
// inp:       [total_padded, 4096] fp32  (d_in[0])
// m_splits:  [n_groups] int32           (d_in[1])
// out:       [sum(m_splits), 4096] fp32
//
// Pure DRAM-bound streaming copy. Persistent grid (148 SMs x 8 CTAs)
// with grid-stride over output rows: no wave-tail quantization, block
// setup amortized over ~10 rows. Front-batched float4 loads (MLP=4),
// default-policy stores (R3 showed __stcs is a slight loss).

static constexpr int HIDDEN = 4096;
static constexpr int VECS_PER_ROW = HIDDEN / 4;  // 1024 float4 per row
static constexpr int THREADS = 256;
static constexpr int VPT = VECS_PER_ROW / THREADS;  // 4 float4 per thread
static constexpr int GRID = 148 * 8;                // one full wave

__global__ void __launch_bounds__(THREADS, 8)
unpad_gather_kernel(const float4* __restrict__ in,
                    const int* __restrict__ m_splits,
                    int n_groups,
                    int n_rows,
                    float4* __restrict__ out)
{
    for (int row = blockIdx.x; row < n_rows; row += GRID) {
        // Map output row -> source row. n_groups is tiny (8); L1-resident.
        long long cum = 0;      // cumulative valid rows (output offset)
        long long pad_off = 0;  // cumulative padded rows (input offset)
        long long src_row = 0;
#pragma unroll 1
        for (int g = 0; g < n_groups; ++g) {
            const long long m = (long long)m_splits[g];
            if (row < cum + m) {
                src_row = pad_off + (row - cum);
                break;
            }
            cum += m;
            pad_off += ((m + 255LL) >> 8) << 8;  // pad to 256
        }

        const float4* __restrict__ src =
            in + src_row * VECS_PER_ROW + threadIdx.x;
        float4* __restrict__ dst =
            out + (long long)row * VECS_PER_ROW + threadIdx.x;

        // Front-batch all loads: 4 independent LDG.128 in flight per thread.
        float4 v[VPT];
#pragma unroll
        for (int i = 0; i < VPT; ++i)
            v[i] = src[i * THREADS];
#pragma unroll
        for (int i = 0; i < VPT; ++i)
            dst[i * THREADS] = v[i];
    }
}

extern "C" void kernel_launch(void* const* d_in, const int* in_sizes, int n_in,
                              void* d_out, int out_size)
{
    const float4* in       = (const float4*)d_in[0];
    const int*    m_splits = (const int*)d_in[1];
    const int     n_groups = in_sizes[1];

    float4* out = (float4*)d_out;
    const int n_rows = out_size / HIDDEN;  // total valid rows

    unpad_gather_kernel<<<GRID, THREADS>>>(in, m_splits, n_groups, n_rows, out);
}

// round 5
// speedup vs baseline: 1.1214x; 1.1214x over previous
#include <cuda_runtime.h>
#include <stdint.h>

// Fp8Unpadding: gather valid rows out of 256-padded groups.
// inp:       [total_padded, 4096] fp32  (d_in[0])
// m_splits:  [n_groups] int32           (d_in[1])
// out:       [sum(m_splits), 4096] fp32
//
// DRAM-bound streaming gather. Converged config (R2 shape):
//   - one block per output row (12166 blocks; HW overlap beats persistent
//     grid, which serialized rows within a block -- R4 regression)
//   - 256 threads, 4 float4 per thread, front-batched loads (MLP=4)
//   - default-policy stores (__stcs tested slightly negative in R3)
//   - 32-bit index math (max vec index 12.8M << 2^31)

static constexpr int HIDDEN = 4096;
static constexpr int VECS_PER_ROW = HIDDEN / 4;   // 1024 float4 per row
static constexpr int THREADS = 256;
static constexpr int VPT = VECS_PER_ROW / THREADS;  // 4

__global__ void __launch_bounds__(THREADS, 8)
unpad_gather_kernel(const float4* __restrict__ in,
                    const int* __restrict__ m_splits,
                    int n_groups,
                    float4* __restrict__ out)
{
    const int row = blockIdx.x;

    // Map output row -> source row. n_groups is tiny (8); L1-resident.
    int cum = 0;      // cumulative valid rows (output offset)
    int pad_off = 0;  // cumulative padded rows (input offset)
    int src_row = 0;
#pragma unroll 1
    for (int g = 0; g < n_groups; ++g) {
        const int m = m_splits[g];
        if (row < cum + m) {
            src_row = pad_off + (row - cum);
            break;
        }
        cum += m;
        pad_off += ((m + 255) >> 8) << 8;  // pad to 256
    }

    const float4* __restrict__ src = in  + src_row * VECS_PER_ROW + threadIdx.x;
    float4*       __restrict__ dst = out + row     * VECS_PER_ROW + threadIdx.x;

    // Front-batch all loads: 4 independent LDG.128 in flight per thread,
    // then the stores.
    float4 v[VPT];
#pragma unroll
    for (int i = 0; i < VPT; ++i)
        v[i] = src[i * THREADS];
#pragma unroll
    for (int i = 0; i < VPT; ++i)
        dst[i * THREADS] = v[i];
}

extern "C" void kernel_launch(void* const* d_in, const int* in_sizes, int n_in,
                              void* d_out, int out_size)
{
    const float4* in       = (const float4*)d_in[0];
    const int*    m_splits = (const int*)d_in[1];
    const int     n_groups = in_sizes[1];

    float4* out = (float4*)d_out;
    const int n_rows = out_size / HIDDEN;  // total valid rows

    unpad_gather_kernel<<<n_rows, THREADS>>>(in, m_splits, n_groups, out);
}